// round 1
// baseline (speedup 1.0000x reference)
#include <cuda_runtime.h>
#include <math.h>

// GraphContrastiveLoss: B=64, N=4096, D=256
// inputs (metadata order):
//  0: node_embeddings f32 [B,N,D]
//  1: graph_labels    i32 [B]   (unused by reference math)
//  2: anchor_idx      i32 [B]
//  3: pos_idx         i32 [B]
//  4: neg_graph_idx   i32 [B]
//  5: neg_node_idx    i32 [B]
// output: f32 scalar

#define B_ 64
#define N_ 4096
#define D_ 256
#define TEMP_INV 10.0f
#define EPS_ 1e-8f

__device__ __forceinline__ float warp_sum(float v) {
    #pragma unroll
    for (int off = 16; off > 0; off >>= 1)
        v += __shfl_xor_sync(0xFFFFFFFFu, v, off);
    return v;
}

__global__ __launch_bounds__(1024, 1)
void gcl_kernel(const float* __restrict__ emb,
                const int* __restrict__ anchor_idx,
                const int* __restrict__ pos_idx,
                const int* __restrict__ neg_gidx,
                const int* __restrict__ neg_nidx,
                float* __restrict__ out) {
    __shared__ float s_loss[B_];

    const int tid  = threadIdx.x;
    const int warp = tid >> 5;
    const int lane = tid & 31;

    // Each warp handles samples warp and warp+32
    #pragma unroll
    for (int rep = 0; rep < 2; rep++) {
        const int b = warp + rep * 32;

        const int ai = anchor_idx[b];
        const int pi = pos_idx[b];
        const int ng = neg_gidx[b];
        const int nn = neg_nidx[b];

        const float4* a_ptr = (const float4*)(emb + ((size_t)b  * N_ + ai) * D_);
        const float4* p_ptr = (const float4*)(emb + ((size_t)b  * N_ + pi) * D_);
        const float4* n_ptr = (const float4*)(emb + ((size_t)ng * N_ + nn) * D_);

        // D=256 floats = 64 float4; lane reads [lane] and [lane+32]
        float4 a0 = a_ptr[lane], a1 = a_ptr[lane + 32];
        float4 p0 = p_ptr[lane], p1 = p_ptr[lane + 32];
        float4 n0 = n_ptr[lane], n1 = n_ptr[lane + 32];

        float dot_ap = a0.x*p0.x + a0.y*p0.y + a0.z*p0.z + a0.w*p0.w
                     + a1.x*p1.x + a1.y*p1.y + a1.z*p1.z + a1.w*p1.w;
        float dot_an = a0.x*n0.x + a0.y*n0.y + a0.z*n0.z + a0.w*n0.w
                     + a1.x*n1.x + a1.y*n1.y + a1.z*n1.z + a1.w*n1.w;
        float na = a0.x*a0.x + a0.y*a0.y + a0.z*a0.z + a0.w*a0.w
                 + a1.x*a1.x + a1.y*a1.y + a1.z*a1.z + a1.w*a1.w;
        float np = p0.x*p0.x + p0.y*p0.y + p0.z*p0.z + p0.w*p0.w
                 + p1.x*p1.x + p1.y*p1.y + p1.z*p1.z + p1.w*p1.w;
        float nn2 = n0.x*n0.x + n0.y*n0.y + n0.z*n0.z + n0.w*n0.w
                  + n1.x*n1.x + n1.y*n1.y + n1.z*n1.z + n1.w*n1.w;

        dot_ap = warp_sum(dot_ap);
        dot_an = warp_sum(dot_an);
        na     = warp_sum(na);
        np     = warp_sum(np);
        nn2    = warp_sum(nn2);

        if (lane == 0) {
            float norm_a = fmaxf(sqrtf(na),  EPS_);
            float norm_p = fmaxf(sqrtf(np),  EPS_);
            float norm_n = fmaxf(sqrtf(nn2), EPS_);
            float pos_sim = dot_ap / (norm_a * norm_p) * TEMP_INV;
            float neg_sim = dot_an / (norm_a * norm_n) * TEMP_INV;
            float x = neg_sim - pos_sim;
            // logaddexp(0, x) = log1p(exp(x)), numerically stable form
            float loss = (x > 0.0f) ? (x + log1pf(expf(-x))) : log1pf(expf(x));
            s_loss[b] = loss;
        }
    }

    __syncthreads();

    // Block reduce 64 values with warp 0
    if (warp == 0) {
        float v = s_loss[lane] + s_loss[lane + 32];
        v = warp_sum(v);
        if (lane == 0)
            out[0] = v * (1.0f / (float)B_);
    }
}

extern "C" void kernel_launch(void* const* d_in, const int* in_sizes, int n_in,
                              void* d_out, int out_size) {
    const float* emb        = (const float*)d_in[0];
    const int*   anchor_idx = (const int*)d_in[2];
    const int*   pos_idx    = (const int*)d_in[3];
    const int*   neg_gidx   = (const int*)d_in[4];
    const int*   neg_nidx   = (const int*)d_in[5];
    float*       out        = (float*)d_out;

    gcl_kernel<<<1, 1024>>>(emb, anchor_idx, pos_idx, neg_gidx, neg_nidx, out);
}

// round 3
// speedup vs baseline: 1.0811x; 1.0811x over previous
#include <cuda_runtime.h>
#include <math.h>

// GraphContrastiveLoss: B=64, N=4096, D=256
// inputs (metadata order):
//  0: node_embeddings f32 [B,N,D]
//  1: graph_labels    i32 [B]   (unused by reference math)
//  2: anchor_idx      i32 [B]
//  3: pos_idx         i32 [B]
//  4: neg_graph_idx   i32 [B]
//  5: neg_node_idx    i32 [B]
// output: f32 scalar

#define B_ 64
#define N_ 4096
#define D_ 256
#define TEMP_INV 10.0f
#define EPS_ 1e-8f

// Cross-block scratch (no device mallocs allowed).
__device__ float        g_loss[B_];
__device__ unsigned int g_count = 0;   // atomicInc wrap-at-64 self-resets each call

__device__ __forceinline__ float warp_sum(float v) {
    #pragma unroll
    for (int off = 16; off > 0; off >>= 1)
        v += __shfl_xor_sync(0xFFFFFFFFu, v, off);
    return v;
}

__global__ __launch_bounds__(32, 1)
void gcl_kernel(const float* __restrict__ emb,
                const int* __restrict__ anchor_idx,
                const int* __restrict__ pos_idx,
                const int* __restrict__ neg_gidx,
                const int* __restrict__ neg_nidx,
                float* __restrict__ out) {
    const int b    = blockIdx.x;
    const int lane = threadIdx.x;

    // One dependent index round-trip (4 independent scalar loads).
    const int ai = __ldg(&anchor_idx[b]);
    const int pi = __ldg(&pos_idx[b]);
    const int ng = __ldg(&neg_gidx[b]);
    const int nn = __ldg(&neg_nidx[b]);

    const float4* a_ptr = (const float4*)(emb + ((size_t)b  * N_ + ai) * D_);
    const float4* p_ptr = (const float4*)(emb + ((size_t)b  * N_ + pi) * D_);
    const float4* n_ptr = (const float4*)(emb + ((size_t)ng * N_ + nn) * D_);

    // 6 independent LDG.128 per lane (MLP=6), covering 3 vectors of D=256.
    float4 a0 = a_ptr[lane], a1 = a_ptr[lane + 32];
    float4 p0 = p_ptr[lane], p1 = p_ptr[lane + 32];
    float4 n0 = n_ptr[lane], n1 = n_ptr[lane + 32];

    float dot_ap = a0.x*p0.x + a0.y*p0.y + a0.z*p0.z + a0.w*p0.w
                 + a1.x*p1.x + a1.y*p1.y + a1.z*p1.z + a1.w*p1.w;
    float dot_an = a0.x*n0.x + a0.y*n0.y + a0.z*n0.z + a0.w*n0.w
                 + a1.x*n1.x + a1.y*n1.y + a1.z*n1.z + a1.w*n1.w;
    float na  = a0.x*a0.x + a0.y*a0.y + a0.z*a0.z + a0.w*a0.w
              + a1.x*a1.x + a1.y*a1.y + a1.z*a1.z + a1.w*a1.w;
    float np  = p0.x*p0.x + p0.y*p0.y + p0.z*p0.z + p0.w*p0.w
              + p1.x*p1.x + p1.y*p1.y + p1.z*p1.z + p1.w*p1.w;
    float nn2 = n0.x*n0.x + n0.y*n0.y + n0.z*n0.z + n0.w*n0.w
              + n1.x*n1.x + n1.y*n1.y + n1.z*n1.z + n1.w*n1.w;

    // Interleaved butterfly reductions (5 values pipeline through the shuffles).
    dot_ap = warp_sum(dot_ap);
    dot_an = warp_sum(dot_an);
    na     = warp_sum(na);
    np     = warp_sum(np);
    nn2    = warp_sum(nn2);

    unsigned int old = 0;
    if (lane == 0) {
        float norm_a = fmaxf(sqrtf(na),  EPS_);
        float norm_p = fmaxf(sqrtf(np),  EPS_);
        float norm_n = fmaxf(sqrtf(nn2), EPS_);
        float pos_sim = dot_ap / (norm_a * norm_p) * TEMP_INV;
        float neg_sim = dot_an / (norm_a * norm_n) * TEMP_INV;
        float x = neg_sim - pos_sim;
        // logaddexp(0, x) = log1p(exp(x)), numerically stable both directions
        float loss = (x > 0.0f) ? (x + log1pf(expf(-x))) : log1pf(expf(x));
        g_loss[b] = loss;
        __threadfence();
        // wrap-at-64: returns old value, stores 0 when old==63 → self-reset
        old = atomicInc(&g_count, B_ - 1);
    }

    // Last block to arrive performs the deterministic final reduction.
    const bool is_last = (__shfl_sync(0xFFFFFFFFu, old, 0) == B_ - 1);
    if (is_last) {
        __threadfence();
        float v = g_loss[lane] + g_loss[lane + 32];
        v = warp_sum(v);
        if (lane == 0)
            out[0] = v * (1.0f / (float)B_);
    }
}

extern "C" void kernel_launch(void* const* d_in, const int* in_sizes, int n_in,
                              void* d_out, int out_size) {
    const float* emb        = (const float*)d_in[0];
    const int*   anchor_idx = (const int*)d_in[2];
    const int*   pos_idx    = (const int*)d_in[3];
    const int*   neg_gidx   = (const int*)d_in[4];
    const int*   neg_nidx   = (const int*)d_in[5];
    float*       out        = (float*)d_out;

    gcl_kernel<<<B_, 32>>>(emb, anchor_idx, pos_idx, neg_gidx, neg_nidx, out);
}